// round 2
// baseline (speedup 1.0000x reference)
#include <cuda_runtime.h>

// Problem sizes (fixed by the dataset)
#define B_  32
#define S_  512
#define H_  768
#define MS_ 128
#define SL_ 8
#define M_  (B_ * S_)        // 16384 rows of X
#define NT_ 12               // H_/64 n-tiles in the GEMM

#define NEG_INF -1e30f

// Scratch: partial logits per n-tile (deterministic reduction, no atomics)
__device__ float g_part[NT_ * M_];

// ---------------------------------------------------------------------------
// fast tanh: tanh(x) = 1 - 2/(exp(2x)+1). 2 MUFU (EX2 + RCP), abs err ~1e-6.
// ---------------------------------------------------------------------------
__device__ __forceinline__ float tanh_fast(float x) {
    float e = __expf(2.0f * x);
    return 1.0f - __fdividef(2.0f, e + 1.0f);
}

// packed f32x2 helpers
#define PACK2(d, lo, hi) asm("mov.b64 %0, {%1, %2};" : "=l"(d) : "f"(lo), "f"(hi))
#define FMA2(acc, a, b)  asm("fma.rn.f32x2 %0, %1, %2, %0;" : "+l"(acc) : "l"(a), "l"(b))
#define UNPACK2(lo, hi, s) asm("mov.b64 {%0, %1}, %2;" : "=f"(lo), "=f"(hi) : "l"(s))

// ---------------------------------------------------------------------------
// Kernel 1: out_vectors = masked segment max (or pad row S-2)
// grid = B*MS blocks, 192 threads (each thread one float4 of H=768)
// NOTE: harness converts bool inputs to int32 — masks are const int*.
// ---------------------------------------------------------------------------
__global__ void gather_max_kernel(const float* __restrict__ X,
                                  const int* __restrict__ segments,
                                  const int* __restrict__ seg_mask,
                                  const int* __restrict__ idx_mask,
                                  float* __restrict__ out) {
    int bm = blockIdx.x;           // b*MS + ms
    int b  = bm >> 7;              // MS_ = 128
    int t  = threadIdx.x;          // 0..191

    __shared__ int sidx[SL_];
    __shared__ int svalid[SL_];
    if (t < SL_) {
        sidx[t]   = segments[bm * SL_ + t];
        svalid[t] = idx_mask[bm * SL_ + t];
    }
    __syncthreads();

    const float4* Xb = (const float4*)(X + (size_t)b * S_ * H_);
    bool ok = seg_mask[bm] != 0;

    float4 r;
    if (!ok) {
        r = Xb[(size_t)(S_ - 2) * (H_ / 4) + t];   // pad_vec = X[b, S-2, :]
    } else {
        r = make_float4(NEG_INF, NEG_INF, NEG_INF, NEG_INF);
#pragma unroll
        for (int sl = 0; sl < SL_; sl++) {
            if (svalid[sl]) {
                float4 v = Xb[(size_t)sidx[sl] * (H_ / 4) + t];
                r.x = fmaxf(r.x, v.x);
                r.y = fmaxf(r.y, v.y);
                r.z = fmaxf(r.z, v.z);
                r.w = fmaxf(r.w, v.w);
            }
        }
    }
    ((float4*)out)[(size_t)bm * (H_ / 4) + t] = r;
}

// ---------------------------------------------------------------------------
// Kernel 2: z = X @ W_attn (16384 x 768 x 768) with fused epilogue:
//   partial_logit[ntile][m] = sum_{n in tile} tanh(z[m][n] + b_attn[n]) * w_ctx[n]
// Tile: BM=128, BN=64, BK=16; 256 threads; per-thread 8m x 4n via 16
// packed fma.rn.f32x2 per k-step (m-pairs in the f32x2 lanes).
// ---------------------------------------------------------------------------
__global__ __launch_bounds__(256) void gemm_logits_kernel(
    const float* __restrict__ X, const float* __restrict__ W,
    const float* __restrict__ b_attn, const float* __restrict__ w_ctx) {

    const int BM = 128, BN = 64, BK = 16;
    const int AS_STRIDE = 132;   // padded (16B-aligned rows, reduced bank conflicts)

    __shared__ float As[BK][AS_STRIDE];   // k-major, m contiguous
    __shared__ float Bs[BK][BN];

    int tid = threadIdx.x;
    int tx  = tid & 15;     // n-group: 4 cols each
    int ty  = tid >> 4;     // m-group: 8 rows each
    int m0  = blockIdx.y * BM;
    int n0  = blockIdx.x * BN;

    unsigned long long acc[16];
#pragma unroll
    for (int i = 0; i < 16; i++) acc[i] = 0ull;

    for (int kt = 0; kt < H_; kt += BK) {
        // --- load A tile: 128m x 16k (each thread 2 float4 along k) ---
#pragma unroll
        for (int i = 0; i < 2; i++) {
            int chunk = tid + i * 256;          // 0..511
            int m  = chunk >> 2;
            int kc = chunk & 3;
            float4 v = *(const float4*)(X + (size_t)(m0 + m) * H_ + kt + kc * 4);
            As[kc * 4 + 0][m] = v.x;
            As[kc * 4 + 1][m] = v.y;
            As[kc * 4 + 2][m] = v.z;
            As[kc * 4 + 3][m] = v.w;
        }
        // --- load B tile: 16k x 64n (1 float4 per thread, coalesced) ---
        {
            int k  = tid >> 4;
            int nc = tid & 15;
            float4 v = *(const float4*)(W + (size_t)(kt + k) * H_ + n0 + nc * 4);
            *(float4*)&Bs[k][nc * 4] = v;
        }
        __syncthreads();

#pragma unroll
        for (int k = 0; k < BK; k++) {
            float4 a0 = *(const float4*)&As[k][ty * 8];
            float4 a1 = *(const float4*)&As[k][ty * 8 + 4];
            float4 bv = *(const float4*)&Bs[k][tx * 4];
            unsigned long long ap0, ap1, ap2, ap3, bd0, bd1, bd2, bd3;
            PACK2(ap0, a0.x, a0.y);
            PACK2(ap1, a0.z, a0.w);
            PACK2(ap2, a1.x, a1.y);
            PACK2(ap3, a1.z, a1.w);
            PACK2(bd0, bv.x, bv.x);
            PACK2(bd1, bv.y, bv.y);
            PACK2(bd2, bv.z, bv.z);
            PACK2(bd3, bv.w, bv.w);
            FMA2(acc[0],  ap0, bd0); FMA2(acc[1],  ap0, bd1);
            FMA2(acc[2],  ap0, bd2); FMA2(acc[3],  ap0, bd3);
            FMA2(acc[4],  ap1, bd0); FMA2(acc[5],  ap1, bd1);
            FMA2(acc[6],  ap1, bd2); FMA2(acc[7],  ap1, bd3);
            FMA2(acc[8],  ap2, bd0); FMA2(acc[9],  ap2, bd1);
            FMA2(acc[10], ap2, bd2); FMA2(acc[11], ap2, bd3);
            FMA2(acc[12], ap3, bd0); FMA2(acc[13], ap3, bd1);
            FMA2(acc[14], ap3, bd2); FMA2(acc[15], ap3, bd3);
        }
        __syncthreads();
    }

    // --- fused epilogue: tanh + dot with w_ctx, reduce over the 64-n tile ---
    float bn[4], wn[4];
    int gnb = n0 + tx * 4;
#pragma unroll
    for (int j = 0; j < 4; j++) {
        bn[j] = b_attn[gnb + j];
        wn[j] = w_ctx[gnb + j];
    }

    float p[8];
#pragma unroll
    for (int i = 0; i < 4; i++) {       // m-pair
        float slo = 0.f, shi = 0.f;
#pragma unroll
        for (int j = 0; j < 4; j++) {
            float lo, hi;
            UNPACK2(lo, hi, acc[i * 4 + j]);
            slo += tanh_fast(lo + bn[j]) * wn[j];
            shi += tanh_fast(hi + bn[j]) * wn[j];
        }
        p[2 * i]     = slo;
        p[2 * i + 1] = shi;
    }

    // reduce across the 16 tx lanes (same ty) — xor<16 stays in the 16-lane half
#pragma unroll
    for (int off = 1; off < 16; off <<= 1) {
#pragma unroll
        for (int r = 0; r < 8; r++)
            p[r] += __shfl_xor_sync(0xffffffffu, p[r], off);
    }
    if (tx == 0) {
#pragma unroll
        for (int r = 0; r < 8; r++)
            g_part[blockIdx.x * M_ + m0 + ty * 8 + r] = p[r];
    }
}

// ---------------------------------------------------------------------------
// Kernel 3: per-b softmax over S of (sum of partials), then
//   sent_repr[b,h] = sum_s softmax(logits)[s] * X[b,s,h]
// grid (B, H/128), 128 threads; softmax recomputed per h-chunk (cheap).
// ---------------------------------------------------------------------------
__global__ __launch_bounds__(128) void softmax_repr_kernel(
    const float* __restrict__ X, float* __restrict__ sent) {

    int b  = blockIdx.x;
    int hc = blockIdx.y;
    int t  = threadIdx.x;

    __shared__ float lg[S_];
    __shared__ float red[128];

    // logits = sum of 12 partials
    for (int s = t; s < S_; s += 128) {
        float v = 0.f;
#pragma unroll
        for (int nt = 0; nt < NT_; nt++) v += g_part[nt * M_ + b * S_ + s];
        lg[s] = v;
    }
    __syncthreads();

    // max
    float mx = -1e30f;
    for (int s = t; s < S_; s += 128) mx = fmaxf(mx, lg[s]);
    red[t] = mx;
    __syncthreads();
    for (int o = 64; o > 0; o >>= 1) {
        if (t < o) red[t] = fmaxf(red[t], red[t + o]);
        __syncthreads();
    }
    mx = red[0];
    __syncthreads();

    // exp + sum
    float sm = 0.f;
    for (int s = t; s < S_; s += 128) {
        float e = __expf(lg[s] - mx);
        lg[s] = e;
        sm += e;
    }
    red[t] = sm;
    __syncthreads();
    for (int o = 64; o > 0; o >>= 1) {
        if (t < o) red[t] += red[t + o];
        __syncthreads();
    }
    float inv = 1.0f / red[0];
    __syncthreads();

    // weighted sum over S for this thread's h column
    int h = hc * 128 + t;
    const float* Xb = X + (size_t)b * S_ * H_ + h;
    float acc = 0.f;
#pragma unroll 8
    for (int s = 0; s < S_; s++)
        acc = fmaf(lg[s], Xb[(size_t)s * H_], acc);

    sent[b * H_ + h] = acc * inv;
}

// ---------------------------------------------------------------------------
// launch
// inputs (metadata order):
//  0 transformer_out f32 [32,512,768]
//  1 segments        i32 [32,128,8]
//  2 segments_mask   bool->int32 [32,128]
//  3 segments_indices_mask bool->int32 [32,128,8]
//  4 W_attn f32 [768,768]
//  5 b_attn f32 [768]
//  6 w_ctx  f32 [768,1]
// output: out_vectors [32,128,768] then sent_repr [32,768], concatenated
// ---------------------------------------------------------------------------
extern "C" void kernel_launch(void* const* d_in, const int* in_sizes, int n_in,
                              void* d_out, int out_size) {
    const float* X       = (const float*)d_in[0];
    const int* segments  = (const int*)d_in[1];
    const int* smask     = (const int*)d_in[2];
    const int* imask     = (const int*)d_in[3];
    const float* W       = (const float*)d_in[4];
    const float* b_attn  = (const float*)d_in[5];
    const float* w_ctx   = (const float*)d_in[6];

    float* out_vectors = (float*)d_out;
    float* sent        = (float*)d_out + (size_t)B_ * MS_ * H_;

    gather_max_kernel<<<B_ * MS_, 192>>>(X, segments, smask, imask, out_vectors);
    gemm_logits_kernel<<<dim3(NT_, M_ / 128), 256>>>(X, W, b_attn, w_ctx);
    softmax_repr_kernel<<<dim3(B_, H_ / 128), 128>>>(X, sent);
}

// round 4
// speedup vs baseline: 1.5979x; 1.5979x over previous
#include <cuda_runtime.h>
#include <cuda_bf16.h>
#include <cstdint>

// Problem sizes (fixed by the dataset)
#define B_  32
#define S_  512
#define H_  768
#define MS_ 128
#define SL_ 8
#define M_  (B_ * S_)        // 16384 rows of X
#define NT_ 24               // partial-logit slices (6 n-blocks x 4 n-warps)

#define NEG_INF -1e30f

// Scratch (device globals: no allocation allowed)
__device__ float g_part[NT_ * M_];                 // partial logits per n-slice
__device__ __nv_bfloat16 Wt_hi[H_ * H_];           // W^T split, hi bf16
__device__ __nv_bfloat16 Wt_lo[H_ * H_];           // W^T split, lo bf16

// ---------------------------------------------------------------------------
// helpers
// ---------------------------------------------------------------------------
__device__ __forceinline__ uint32_t smem_u32(const void* p) {
    uint32_t a;
    asm("{ .reg .u64 t; cvta.to.shared.u64 t, %1; cvt.u32.u64 %0, t; }"
        : "=r"(a) : "l"(p));
    return a;
}

#define CP_ASYNC4(dst, src) \
    asm volatile("cp.async.ca.shared.global [%0], [%1], 4;" :: "r"(dst), "l"(src))
#define CP_COMMIT() asm volatile("cp.async.commit_group;" ::: "memory")
#define CP_WAIT0()  asm volatile("cp.async.wait_group 0;" ::: "memory")

__device__ __forceinline__ void mma_bf16(float* d, const uint32_t* a, const uint32_t* b) {
    asm volatile("mma.sync.aligned.m16n8k16.row.col.f32.bf16.bf16.f32 "
        "{%0,%1,%2,%3}, {%4,%5,%6,%7}, {%8,%9}, {%0,%1,%2,%3};"
        : "+f"(d[0]), "+f"(d[1]), "+f"(d[2]), "+f"(d[3])
        : "r"(a[0]), "r"(a[1]), "r"(a[2]), "r"(a[3]), "r"(b[0]), "r"(b[1]));
}

// fast tanh: tanh(x) = 1 - 2/(exp(2x)+1). 2 MUFU, abs err ~1e-6.
__device__ __forceinline__ float tanh_fast(float x) {
    float e = __expf(2.0f * x);
    return 1.0f - __fdividef(2.0f, e + 1.0f);
}

// ---------------------------------------------------------------------------
// Kernel 0: transpose + bf16-split W -> Wt_hi/Wt_lo (Wt[n][k] = W[k][n])
// ---------------------------------------------------------------------------
__global__ void wsplit_kernel(const float* __restrict__ W) {
    __shared__ float t[32][33];
    int n0 = blockIdx.x * 32, k0 = blockIdx.y * 32;
    int tx = threadIdx.x, ty = threadIdx.y;
    t[ty][tx] = W[(size_t)(k0 + ty) * H_ + n0 + tx];
    __syncthreads();
    float x = t[tx][ty];                       // W[k0+tx][n0+ty]
    __nv_bfloat16 h = __float2bfloat16(x);
    size_t o = (size_t)(n0 + ty) * H_ + k0 + tx;
    Wt_hi[o] = h;
    Wt_lo[o] = __float2bfloat16(x - __bfloat162float(h));
}

// ---------------------------------------------------------------------------
// Kernel 1: out_vectors = masked segment max (or pad row S-2)
// ---------------------------------------------------------------------------
__global__ void gather_max_kernel(const float* __restrict__ X,
                                  const int* __restrict__ segments,
                                  const int* __restrict__ seg_mask,
                                  const int* __restrict__ idx_mask,
                                  float* __restrict__ out) {
    int bm = blockIdx.x;
    int b  = bm >> 7;
    int t  = threadIdx.x;

    __shared__ int sidx[SL_];
    __shared__ int svalid[SL_];
    if (t < SL_) {
        sidx[t]   = segments[bm * SL_ + t];
        svalid[t] = idx_mask[bm * SL_ + t];
    }
    __syncthreads();

    const float4* Xb = (const float4*)(X + (size_t)b * S_ * H_);
    bool ok = seg_mask[bm] != 0;

    float4 r;
    if (!ok) {
        r = Xb[(size_t)(S_ - 2) * (H_ / 4) + t];
    } else {
        r = make_float4(NEG_INF, NEG_INF, NEG_INF, NEG_INF);
#pragma unroll
        for (int sl = 0; sl < SL_; sl++) {
            if (svalid[sl]) {
                float4 v = Xb[(size_t)sidx[sl] * (H_ / 4) + t];
                r.x = fmaxf(r.x, v.x);
                r.y = fmaxf(r.y, v.y);
                r.z = fmaxf(r.z, v.z);
                r.w = fmaxf(r.w, v.w);
            }
        }
    }
    ((float4*)out)[(size_t)bm * (H_ / 4) + t] = r;
}

// ---------------------------------------------------------------------------
// Kernel 2: split-bf16 mma.sync GEMM + fused tanh/w_ctx epilogue
//   grid (6 n-blocks, 128 m-tiles), 256 threads (8 warps, warp tile 64x32)
//   BM=128 BN=128 BK=32, double-buffered fragment-major SMEM
// ---------------------------------------------------------------------------
#define SA_HI 0
#define SA_LO 8192
#define SB_HI 16384
#define SB_LO 24576
#define BUFSZ 32768
#define SM_REQ (2 * BUFSZ)

// A fragment word (m, kp): lane/reg placement for mma.m16n8k16 A operand
__device__ __forceinline__ uint32_t a_woff(int m, int kp) {
    int mt   = m >> 4;
    int ks   = kp >> 3;
    int lane = (m & 7) * 4 + (kp & 3);
    int r    = ((m >> 3) & 1) + 2 * ((kp >> 2) & 1);
    return (uint32_t)((((mt * 2 + ks) * 32 + lane) * 4 + r) * 4);
}
// B fragment word (n, kp)
__device__ __forceinline__ uint32_t b_woff(int n, int kp) {
    int nt   = n >> 3;
    int ks   = kp >> 3;
    int lane = (n & 7) * 4 + (kp & 3);
    int r    = (kp >> 2) & 1;
    return (uint32_t)((((nt * 2 + ks) * 32 + lane) * 2 + r) * 4);
}

__global__ __launch_bounds__(256, 2) void gemm_mma_kernel(
    const float* __restrict__ X, const float* __restrict__ b_attn,
    const float* __restrict__ w_ctx) {

    extern __shared__ __align__(128) char smb[];
    uint32_t sbu = smem_u32(smb);

    int tid  = threadIdx.x;
    int wid  = tid >> 5, lane = tid & 31;
    int wm   = wid >> 2, wn = wid & 3;        // warp grid 2(m) x 4(n)
    int m0   = blockIdx.y * 128;
    int n0   = blockIdx.x * 128;

    float d[4][4][4];
#pragma unroll
    for (int i = 0; i < 4; i++)
#pragma unroll
        for (int j = 0; j < 4; j++)
#pragma unroll
            for (int r = 0; r < 4; r++) d[i][j][r] = 0.f;

    float2 av[8];

    // ---- staging helpers (inlined via lambdas) ----
    auto load_A = [&](int kt) {
#pragma unroll
        for (int p = 0; p < 8; p++) {
            int idx = tid + p * 256;
            int m = idx >> 4, kp = idx & 15;
            av[p] = *(const float2*)(X + (size_t)(m0 + m) * H_ + kt + 2 * kp);
        }
    };
    auto store_A = [&](char* buf) {
#pragma unroll
        for (int p = 0; p < 8; p++) {
            int idx = tid + p * 256;
            int m = idx >> 4, kp = idx & 15;
            float x = av[p].x, y = av[p].y;
            __nv_bfloat16 hx = __float2bfloat16(x), hy = __float2bfloat16(y);
            float lx = x - __bfloat162float(hx);
            float ly = y - __bfloat162float(hy);
            __nv_bfloat162 hw; hw.x = hx; hw.y = hy;
            __nv_bfloat162 lw; lw.x = __float2bfloat16(lx); lw.y = __float2bfloat16(ly);
            uint32_t off = a_woff(m, kp);
            *(uint32_t*)(buf + SA_HI + off) = *(uint32_t*)&hw;
            *(uint32_t*)(buf + SA_LO + off) = *(uint32_t*)&lw;
        }
    };
    auto stage_B = [&](int kt, uint32_t buf) {
        const __nv_bfloat16* wh = Wt_hi;
        const __nv_bfloat16* wl = Wt_lo;
#pragma unroll
        for (int p = 0; p < 8; p++) {
            int idx = tid + p * 256;
            int n = idx >> 4, kp = idx & 15;
            size_t e = (size_t)(n0 + n) * H_ + kt + 2 * kp;
            uint32_t off = b_woff(n, kp);
            CP_ASYNC4(buf + SB_HI + off, (const char*)(wh + e));
            CP_ASYNC4(buf + SB_LO + off, (const char*)(wl + e));
        }
    };
    auto compute = [&](const char* buf) {
#pragma unroll
        for (int s = 0; s < 3; s++) {
            const char* Ab = buf + (s < 2 ? SA_HI : SA_LO);
            const char* Bb = buf + (s == 1 ? SB_LO : SB_HI);
#pragma unroll
            for (int ks = 0; ks < 2; ks++) {
                uint32_t a[4][4], b[4][2];
#pragma unroll
                for (int mt = 0; mt < 4; mt++) {
                    uint4 v = *(const uint4*)(Ab +
                        ((((wm * 4 + mt) * 2 + ks) * 32 + lane) * 16));
                    a[mt][0] = v.x; a[mt][1] = v.y; a[mt][2] = v.z; a[mt][3] = v.w;
                }
#pragma unroll
                for (int nt = 0; nt < 4; nt++) {
                    uint2 v = *(const uint2*)(Bb +
                        ((((wn * 4 + nt) * 2 + ks) * 32 + lane) * 8));
                    b[nt][0] = v.x; b[nt][1] = v.y;
                }
#pragma unroll
                for (int mt = 0; mt < 4; mt++)
#pragma unroll
                    for (int nt = 0; nt < 4; nt++)
                        mma_bf16(d[mt][nt], a[mt], b[nt]);
            }
        }
    };

    // ---- prologue: chunk 0 ----
    load_A(0);
    stage_B(0, sbu);
    store_A(smb);
    CP_COMMIT();
    CP_WAIT0();
    __syncthreads();

    // ---- mainloop: 24 chunks of K=32, double-buffered ----
    for (int c = 0; c < 24; c++) {
        char* cur = smb + (c & 1) * BUFSZ;
        if (c < 23) {
            load_A((c + 1) * 32);
            stage_B((c + 1) * 32, sbu + ((c + 1) & 1) * BUFSZ);
            CP_COMMIT();
        }
        compute(cur);
        if (c < 23) {
            store_A(smb + ((c + 1) & 1) * BUFSZ);
            CP_WAIT0();
        }
        __syncthreads();
    }

    // ---- fused epilogue: partial logit = sum_n tanh(z + b) * w ----
    int q = lane & 3, g = lane >> 2;
    float bv[4][2], wv[4][2];
#pragma unroll
    for (int nt = 0; nt < 4; nt++)
#pragma unroll
        for (int c = 0; c < 2; c++) {
            int n = n0 + wn * 32 + nt * 8 + 2 * q + c;
            bv[nt][c] = b_attn[n];
            wv[nt][c] = w_ctx[n];
        }

    int slice = blockIdx.x * 4 + wn;
#pragma unroll
    for (int mt = 0; mt < 4; mt++) {
        float s0 = 0.f, s1 = 0.f;
#pragma unroll
        for (int nt = 0; nt < 4; nt++)
#pragma unroll
            for (int c = 0; c < 2; c++) {
                s0 += tanh_fast(d[mt][nt][c]     + bv[nt][c]) * wv[nt][c];
                s1 += tanh_fast(d[mt][nt][2 + c] + bv[nt][c]) * wv[nt][c];
            }
        s0 += __shfl_xor_sync(0xffffffffu, s0, 1);
        s0 += __shfl_xor_sync(0xffffffffu, s0, 2);
        s1 += __shfl_xor_sync(0xffffffffu, s1, 1);
        s1 += __shfl_xor_sync(0xffffffffu, s1, 2);
        if (q == 0) {
            int mg = m0 + wm * 64 + mt * 16 + g;
            g_part[slice * M_ + mg]     = s0;
            g_part[slice * M_ + mg + 8] = s1;
        }
    }
}

// ---------------------------------------------------------------------------
// Kernel 3: per-b softmax over S, then weighted sum over X
// ---------------------------------------------------------------------------
__global__ __launch_bounds__(128) void softmax_repr_kernel(
    const float* __restrict__ X, float* __restrict__ sent) {

    int b  = blockIdx.x;
    int hc = blockIdx.y;
    int t  = threadIdx.x;

    __shared__ float lg[S_];
    __shared__ float red[128];

    for (int s = t; s < S_; s += 128) {
        float v = 0.f;
#pragma unroll
        for (int nt = 0; nt < NT_; nt++) v += g_part[nt * M_ + b * S_ + s];
        lg[s] = v;
    }
    __syncthreads();

    float mx = -1e30f;
    for (int s = t; s < S_; s += 128) mx = fmaxf(mx, lg[s]);
    red[t] = mx;
    __syncthreads();
    for (int o = 64; o > 0; o >>= 1) {
        if (t < o) red[t] = fmaxf(red[t], red[t + o]);
        __syncthreads();
    }
    mx = red[0];
    __syncthreads();

    float sm = 0.f;
    for (int s = t; s < S_; s += 128) {
        float e = __expf(lg[s] - mx);
        lg[s] = e;
        sm += e;
    }
    red[t] = sm;
    __syncthreads();
    for (int o = 64; o > 0; o >>= 1) {
        if (t < o) red[t] += red[t + o];
        __syncthreads();
    }
    float inv = 1.0f / red[0];
    __syncthreads();

    int h = hc * 128 + t;
    const float* Xb = X + (size_t)b * S_ * H_ + h;
    float acc = 0.f;
#pragma unroll 8
    for (int s = 0; s < S_; s++)
        acc = fmaf(lg[s], Xb[(size_t)s * H_], acc);

    sent[b * H_ + h] = acc * inv;
}

// ---------------------------------------------------------------------------
// launch
// ---------------------------------------------------------------------------
extern "C" void kernel_launch(void* const* d_in, const int* in_sizes, int n_in,
                              void* d_out, int out_size) {
    const float* X       = (const float*)d_in[0];
    const int* segments  = (const int*)d_in[1];
    const int* smask     = (const int*)d_in[2];
    const int* imask     = (const int*)d_in[3];
    const float* W       = (const float*)d_in[4];
    const float* b_attn  = (const float*)d_in[5];
    const float* w_ctx   = (const float*)d_in[6];

    float* out_vectors = (float*)d_out;
    float* sent        = (float*)d_out + (size_t)B_ * MS_ * H_;

    cudaFuncSetAttribute(gemm_mma_kernel,
                         cudaFuncAttributeMaxDynamicSharedMemorySize, SM_REQ);

    wsplit_kernel<<<dim3(24, 24), dim3(32, 32)>>>(W);
    gather_max_kernel<<<B_ * MS_, 192>>>(X, segments, smask, imask, out_vectors);
    gemm_mma_kernel<<<dim3(6, 128), 256, SM_REQ>>>(X, b_attn, w_ctx);
    softmax_repr_kernel<<<dim3(B_, H_ / 128), 128>>>(X, sent);
}

// round 5
// speedup vs baseline: 1.7722x; 1.1091x over previous
#include <cuda_runtime.h>
#include <cuda_bf16.h>
#include <cstdint>

// Problem sizes (fixed by the dataset)
#define B_  32
#define S_  512
#define H_  768
#define MS_ 128
#define SL_ 8
#define M_  (B_ * S_)        // 16384 rows of X
#define NT_ 24               // partial-logit slices (6 n-blocks x 4 n-warps)

#define NEG_INF -1e30f

// Scratch (device globals: no allocation allowed)
__device__ float g_part[NT_ * M_];                 // partial logits per n-slice
__device__ float g_attn[M_];                       // softmax weights a[b,s]
__device__ float g_sacc[B_ * 6 * 8 * 128];         // weighted-sum partials
__device__ __nv_bfloat16 Wt_hi[H_ * H_];           // W^T split, hi bf16
__device__ __nv_bfloat16 Wt_lo[H_ * H_];           // W^T split, lo bf16
__device__ __nv_bfloat16 Xhi[M_ * H_];             // X split, hi bf16
__device__ __nv_bfloat16 Xlo[M_ * H_];             // X split, lo bf16

// ---------------------------------------------------------------------------
// helpers
// ---------------------------------------------------------------------------
__device__ __forceinline__ uint32_t smem_u32(const void* p) {
    uint32_t a;
    asm("{ .reg .u64 t; cvta.to.shared.u64 t, %1; cvt.u32.u64 %0, t; }"
        : "=r"(a) : "l"(p));
    return a;
}

#define CP_ASYNC4(dst, src) \
    asm volatile("cp.async.ca.shared.global [%0], [%1], 4;" :: "r"(dst), "l"(src))
#define CP_COMMIT() asm volatile("cp.async.commit_group;" ::: "memory")
#define CP_WAIT0()  asm volatile("cp.async.wait_group 0;" ::: "memory")

__device__ __forceinline__ void mma_bf16(float* d, const uint32_t* a, const uint32_t* b) {
    asm volatile("mma.sync.aligned.m16n8k16.row.col.f32.bf16.bf16.f32 "
        "{%0,%1,%2,%3}, {%4,%5,%6,%7}, {%8,%9}, {%0,%1,%2,%3};"
        : "+f"(d[0]), "+f"(d[1]), "+f"(d[2]), "+f"(d[3])
        : "r"(a[0]), "r"(a[1]), "r"(a[2]), "r"(a[3]), "r"(b[0]), "r"(b[1]));
}

// fast tanh: tanh(x) = 1 - 2/(exp(2x)+1). 2 MUFU, abs err ~1e-6.
__device__ __forceinline__ float tanh_fast(float x) {
    float e = __expf(2.0f * x);
    return 1.0f - __fdividef(2.0f, e + 1.0f);
}

// ---------------------------------------------------------------------------
// Kernel 0a: transpose + bf16-split W -> Wt_hi/Wt_lo (Wt[n][k] = W[k][n])
// ---------------------------------------------------------------------------
__global__ void wsplit_kernel(const float* __restrict__ W) {
    __shared__ float t[32][33];
    int n0 = blockIdx.x * 32, k0 = blockIdx.y * 32;
    int tx = threadIdx.x, ty = threadIdx.y;
    t[ty][tx] = W[(size_t)(k0 + ty) * H_ + n0 + tx];
    __syncthreads();
    float x = t[tx][ty];                       // W[k0+tx][n0+ty]
    __nv_bfloat16 h = __float2bfloat16(x);
    size_t o = (size_t)(n0 + ty) * H_ + k0 + tx;
    Wt_hi[o] = h;
    Wt_lo[o] = __float2bfloat16(x - __bfloat162float(h));
}

// ---------------------------------------------------------------------------
// Kernel 0b: bf16-split X -> Xhi/Xlo (row-major, same layout as X)
// ---------------------------------------------------------------------------
__global__ __launch_bounds__(256) void xsplit_kernel(const float* __restrict__ X) {
    size_t i = ((size_t)blockIdx.x * 256 + threadIdx.x) * 4;
    float4 v = *(const float4*)(X + i);
    float xs[4] = {v.x, v.y, v.z, v.w};
    __nv_bfloat16 hb[4], lb[4];
#pragma unroll
    for (int e = 0; e < 4; e++) {
        __nv_bfloat16 h = __float2bfloat16(xs[e]);
        hb[e] = h;
        lb[e] = __float2bfloat16(xs[e] - __bfloat162float(h));
    }
    *(uint2*)(Xhi + i) = *(uint2*)hb;
    *(uint2*)(Xlo + i) = *(uint2*)lb;
}

// ---------------------------------------------------------------------------
// Kernel 1: out_vectors = masked segment max (or pad row S-2)
// ---------------------------------------------------------------------------
__global__ void gather_max_kernel(const float* __restrict__ X,
                                  const int* __restrict__ segments,
                                  const int* __restrict__ seg_mask,
                                  const int* __restrict__ idx_mask,
                                  float* __restrict__ out) {
    int bm = blockIdx.x;
    int b  = bm >> 7;
    int t  = threadIdx.x;

    __shared__ int sidx[SL_];
    __shared__ int svalid[SL_];
    if (t < SL_) {
        sidx[t]   = segments[bm * SL_ + t];
        svalid[t] = idx_mask[bm * SL_ + t];
    }
    __syncthreads();

    const float4* Xb = (const float4*)(X + (size_t)b * S_ * H_);
    bool ok = seg_mask[bm] != 0;

    float4 r;
    if (!ok) {
        r = Xb[(size_t)(S_ - 2) * (H_ / 4) + t];
    } else {
        r = make_float4(NEG_INF, NEG_INF, NEG_INF, NEG_INF);
#pragma unroll
        for (int sl = 0; sl < SL_; sl++) {
            if (svalid[sl]) {
                float4 v = Xb[(size_t)sidx[sl] * (H_ / 4) + t];
                r.x = fmaxf(r.x, v.x);
                r.y = fmaxf(r.y, v.y);
                r.z = fmaxf(r.z, v.z);
                r.w = fmaxf(r.w, v.w);
            }
        }
    }
    ((float4*)out)[(size_t)bm * (H_ / 4) + t] = r;
}

// ---------------------------------------------------------------------------
// Kernel 2: split-bf16 mma.sync GEMM + fused tanh/w_ctx epilogue
//   grid (6 n-blocks, 128 m-tiles), 256 threads (8 warps, warp tile 64x32)
//   BM=128 BN=128 BK=32, double-buffered fragment-major SMEM, all cp.async
// ---------------------------------------------------------------------------
#define SA_HI 0
#define SA_LO 8192
#define SB_HI 16384
#define SB_LO 24576
#define BUFSZ 32768
#define SM_REQ (2 * BUFSZ)

// A fragment word (m, kp): lane/reg placement for mma.m16n8k16 A operand
__device__ __forceinline__ uint32_t a_woff(int m, int kp) {
    int mt   = m >> 4;
    int ks   = kp >> 3;
    int lane = (m & 7) * 4 + (kp & 3);
    int r    = ((m >> 3) & 1) + 2 * ((kp >> 2) & 1);
    return (uint32_t)((((mt * 2 + ks) * 32 + lane) * 4 + r) * 4);
}
// B fragment word (n, kp)
__device__ __forceinline__ uint32_t b_woff(int n, int kp) {
    int nt   = n >> 3;
    int ks   = kp >> 3;
    int lane = (n & 7) * 4 + (kp & 3);
    int r    = (kp >> 2) & 1;
    return (uint32_t)((((nt * 2 + ks) * 32 + lane) * 2 + r) * 4);
}

__global__ __launch_bounds__(256, 2) void gemm_mma_kernel(
    const float* __restrict__ b_attn, const float* __restrict__ w_ctx) {

    extern __shared__ __align__(128) char smb[];
    uint32_t sbu = smem_u32(smb);

    int tid  = threadIdx.x;
    int wid  = tid >> 5, lane = tid & 31;
    int wm   = wid >> 2, wn = wid & 3;        // warp grid 2(m) x 4(n)
    int m0   = blockIdx.y * 128;
    int n0   = blockIdx.x * 128;

    float d[4][4][4];
#pragma unroll
    for (int i = 0; i < 4; i++)
#pragma unroll
        for (int j = 0; j < 4; j++)
#pragma unroll
            for (int r = 0; r < 4; r++) d[i][j][r] = 0.f;

    // ---- staging: pure cp.async into fragment-major layout ----
    auto stage_A = [&](int kt, uint32_t buf) {
#pragma unroll
        for (int p = 0; p < 8; p++) {
            int idx = tid + p * 256;           // 0..2047
            int m = idx >> 4, kp = idx & 15;
            size_t e = (size_t)(m0 + m) * H_ + kt + 2 * kp;
            uint32_t off = a_woff(m, kp);
            CP_ASYNC4(buf + SA_HI + off, (const char*)(Xhi + e));
            CP_ASYNC4(buf + SA_LO + off, (const char*)(Xlo + e));
        }
    };
    auto stage_B = [&](int kt, uint32_t buf) {
#pragma unroll
        for (int p = 0; p < 8; p++) {
            int idx = tid + p * 256;
            int n = idx >> 4, kp = idx & 15;
            size_t e = (size_t)(n0 + n) * H_ + kt + 2 * kp;
            uint32_t off = b_woff(n, kp);
            CP_ASYNC4(buf + SB_HI + off, (const char*)(Wt_hi + e));
            CP_ASYNC4(buf + SB_LO + off, (const char*)(Wt_lo + e));
        }
    };
    auto compute = [&](const char* buf) {
#pragma unroll
        for (int s = 0; s < 3; s++) {
            const char* Ab = buf + (s < 2 ? SA_HI : SA_LO);
            const char* Bb = buf + (s == 1 ? SB_LO : SB_HI);
#pragma unroll
            for (int ks = 0; ks < 2; ks++) {
                uint32_t a[4][4], b[4][2];
#pragma unroll
                for (int mt = 0; mt < 4; mt++) {
                    uint4 v = *(const uint4*)(Ab +
                        ((((wm * 4 + mt) * 2 + ks) * 32 + lane) * 16));
                    a[mt][0] = v.x; a[mt][1] = v.y; a[mt][2] = v.z; a[mt][3] = v.w;
                }
#pragma unroll
                for (int nt = 0; nt < 4; nt++) {
                    uint2 v = *(const uint2*)(Bb +
                        ((((wn * 4 + nt) * 2 + ks) * 32 + lane) * 8));
                    b[nt][0] = v.x; b[nt][1] = v.y;
                }
#pragma unroll
                for (int mt = 0; mt < 4; mt++)
#pragma unroll
                    for (int nt = 0; nt < 4; nt++)
                        mma_bf16(d[mt][nt], a[mt], b[nt]);
            }
        }
    };

    // ---- prologue: chunk 0 ----
    stage_A(0, sbu);
    stage_B(0, sbu);
    CP_COMMIT();
    CP_WAIT0();
    __syncthreads();

    // ---- mainloop: 24 chunks of K=32, double-buffered ----
    for (int c = 0; c < 24; c++) {
        const char* cur = smb + (c & 1) * BUFSZ;
        if (c < 23) {
            uint32_t nxt = sbu + ((c + 1) & 1) * BUFSZ;
            stage_A((c + 1) * 32, nxt);
            stage_B((c + 1) * 32, nxt);
            CP_COMMIT();
        }
        compute(cur);
        if (c < 23) CP_WAIT0();
        __syncthreads();
    }

    // ---- fused epilogue: partial logit = sum_n tanh(z + b) * w ----
    int q = lane & 3, g = lane >> 2;
    float bv[4][2], wv[4][2];
#pragma unroll
    for (int nt = 0; nt < 4; nt++)
#pragma unroll
        for (int c = 0; c < 2; c++) {
            int n = n0 + wn * 32 + nt * 8 + 2 * q + c;
            bv[nt][c] = b_attn[n];
            wv[nt][c] = w_ctx[n];
        }

    int slice = blockIdx.x * 4 + wn;
#pragma unroll
    for (int mt = 0; mt < 4; mt++) {
        float s0 = 0.f, s1 = 0.f;
#pragma unroll
        for (int nt = 0; nt < 4; nt++)
#pragma unroll
            for (int c = 0; c < 2; c++) {
                s0 += tanh_fast(d[mt][nt][c]     + bv[nt][c]) * wv[nt][c];
                s1 += tanh_fast(d[mt][nt][2 + c] + bv[nt][c]) * wv[nt][c];
            }
        s0 += __shfl_xor_sync(0xffffffffu, s0, 1);
        s0 += __shfl_xor_sync(0xffffffffu, s0, 2);
        s1 += __shfl_xor_sync(0xffffffffu, s1, 1);
        s1 += __shfl_xor_sync(0xffffffffu, s1, 2);
        if (q == 0) {
            int mg = m0 + wm * 64 + mt * 16 + g;
            g_part[slice * M_ + mg]     = s0;
            g_part[slice * M_ + mg + 8] = s1;
        }
    }
}

// ---------------------------------------------------------------------------
// Kernel 3a: softmax weights a[b,s] from 24 partial-logit slices
// grid = B_, block = 256
// ---------------------------------------------------------------------------
__global__ __launch_bounds__(256) void attn_weights_kernel() {
    int b = blockIdx.x, t = threadIdx.x;
    __shared__ float lg[S_];
    __shared__ float red[256];

    for (int s = t; s < S_; s += 256) {
        float v = 0.f;
#pragma unroll
        for (int nt = 0; nt < NT_; nt++) v += g_part[nt * M_ + b * S_ + s];
        lg[s] = v;
    }
    __syncthreads();

    float mx = fmaxf(lg[t], lg[t + 256]);
    red[t] = mx;
    __syncthreads();
    for (int o = 128; o > 0; o >>= 1) {
        if (t < o) red[t] = fmaxf(red[t], red[t + o]);
        __syncthreads();
    }
    mx = red[0];
    __syncthreads();

    float e0 = __expf(lg[t] - mx);
    float e1 = __expf(lg[t + 256] - mx);
    red[t] = e0 + e1;
    __syncthreads();
    for (int o = 128; o > 0; o >>= 1) {
        if (t < o) red[t] += red[t + o];
        __syncthreads();
    }
    float inv = 1.0f / red[0];

    g_attn[b * S_ + t]       = e0 * inv;
    g_attn[b * S_ + t + 256] = e1 * inv;
}

// ---------------------------------------------------------------------------
// Kernel 3b: partial weighted sums
// grid (B_, 6 h-chunks, 8 s-chunks), block 128
// ---------------------------------------------------------------------------
__global__ __launch_bounds__(128) void wsum_partial_kernel(
    const float* __restrict__ X) {
    int b = blockIdx.x, hc = blockIdx.y, sc = blockIdx.z;
    int t = threadIdx.x;
    int h = hc * 128 + t;

    const float* Xp = X + (size_t)b * S_ * H_ + (size_t)sc * 64 * H_ + h;
    const float* ap = g_attn + b * S_ + sc * 64;

    float acc = 0.f;
#pragma unroll 8
    for (int s = 0; s < 64; s++)
        acc = fmaf(ap[s], Xp[(size_t)s * H_], acc);

    g_sacc[(((b * 6) + hc) * 8 + sc) * 128 + t] = acc;
}

// ---------------------------------------------------------------------------
// Kernel 3c: reduce 8 s-chunk partials -> sent_repr
// grid (B_, 6), block 128
// ---------------------------------------------------------------------------
__global__ __launch_bounds__(128) void wsum_reduce_kernel(float* __restrict__ sent) {
    int b = blockIdx.x, hc = blockIdx.y, t = threadIdx.x;
    const float* p = g_sacc + (((b * 6) + hc) * 8) * 128 + t;
    float acc = 0.f;
#pragma unroll
    for (int sc = 0; sc < 8; sc++) acc += p[sc * 128];
    sent[b * H_ + hc * 128 + t] = acc;
}

// ---------------------------------------------------------------------------
// launch
// ---------------------------------------------------------------------------
extern "C" void kernel_launch(void* const* d_in, const int* in_sizes, int n_in,
                              void* d_out, int out_size) {
    const float* X       = (const float*)d_in[0];
    const int* segments  = (const int*)d_in[1];
    const int* smask     = (const int*)d_in[2];
    const int* imask     = (const int*)d_in[3];
    const float* W       = (const float*)d_in[4];
    const float* b_attn  = (const float*)d_in[5];
    const float* w_ctx   = (const float*)d_in[6];

    float* out_vectors = (float*)d_out;
    float* sent        = (float*)d_out + (size_t)B_ * MS_ * H_;

    cudaFuncSetAttribute(gemm_mma_kernel,
                         cudaFuncAttributeMaxDynamicSharedMemorySize, SM_REQ);

    wsplit_kernel<<<dim3(24, 24), dim3(32, 32)>>>(W);
    xsplit_kernel<<<(M_ * H_ / 4) / 256, 256>>>(X);
    gather_max_kernel<<<B_ * MS_, 192>>>(X, segments, smask, imask, out_vectors);
    gemm_mma_kernel<<<dim3(6, 128), 256, SM_REQ>>>(b_attn, w_ctx);
    attn_weights_kernel<<<B_, 256>>>();
    wsum_partial_kernel<<<dim3(B_, 6, 8), 128>>>(X);
    wsum_reduce_kernel<<<dim3(B_, 6), 128>>>(sent);
}